// round 16
// baseline (speedup 1.0000x reference)
#include <cuda_runtime.h>
#include <cuda_bf16.h>
#include <math_constants.h>
#include <cstdint>

#define N_ROWS 32768
#define D_DIM  256
#define K_CODES 1024
#define MARGIN 3.0e-3f
#define CAP 24
#define NTHR 256
#define ROWS_CTA 256
#define NWARP 8
#define NCHUNK 32
#define CHUNK_CODES 32
#define CHUNK_BYTES 16384

__device__ float  g_b[K_CODES];
__device__ double g_loss = 0.0;
__device__ unsigned g_done = 0;
// pre-swizzled bf16 codebook: 32 chunks x 32 codes x 512B (unit-xor swizzled)
__device__ __align__(128) unsigned char g_eb[K_CODES * D_DIM * 2];

__device__ __forceinline__ uint32_t s2u(const void* p) {
    uint32_t a;
    asm("{ .reg .u64 t; cvta.to.shared.u64 t, %1; cvt.u32.u64 %0, t; }" : "=r"(a) : "l"(p));
    return a;
}
__device__ __forceinline__ uint32_t pbf2(float lo, float hi) {
    uint32_t r;
    asm("{.reg .b16 l,h;\n\tcvt.rn.bf16.f32 l,%1;\n\tcvt.rn.bf16.f32 h,%2;\n\tmov.b32 %0,{l,h};}"
        : "=r"(r) : "f"(lo), "f"(hi));
    return r;
}
__device__ __forceinline__ uint32_t fmap(float f) {
    uint32_t b = __float_as_uint(f);
    return b ^ ((b & 0x80000000u) ? 0xFFFFFFFFu : 0x80000000u);
}
__device__ __forceinline__ float funmap(uint32_t u) {
    uint32_t b = (u & 0x80000000u) ? (u ^ 0x80000000u) : ~u;
    return __uint_as_float(b);
}
#define LDSM4(d, addr) \
    asm volatile("ldmatrix.sync.aligned.m8n8.x4.shared.b16 {%0,%1,%2,%3}, [%4];" \
        : "=r"((d)[0]), "=r"((d)[1]), "=r"((d)[2]), "=r"((d)[3]) : "r"(addr))
#define MMA16816(c, a, b0, b1) \
    asm volatile("mma.sync.aligned.m16n8k16.row.col.f32.bf16.bf16.f32 " \
        "{%0,%1,%2,%3}, {%4,%5,%6,%7}, {%8,%9}, {%0,%1,%2,%3};" \
        : "+f"((c)[0]), "+f"((c)[1]), "+f"((c)[2]), "+f"((c)[3]) \
        : "r"((a)[0]), "r"((a)[1]), "r"((a)[2]), "r"((a)[3]), "r"(b0), "r"(b1))
#define MB_INIT(mb, c) \
    asm volatile("mbarrier.init.shared.b64 [%0], %1;" :: "r"((uint32_t)(mb)), "r"((uint32_t)(c)) : "memory")
#define MB_EXPECT(mb, n) \
    asm volatile("mbarrier.arrive.expect_tx.shared.b64 _, [%0], %1;" :: "r"((uint32_t)(mb)), "r"((uint32_t)(n)) : "memory")
#define MB_ARRIVE(mb) \
    asm volatile("mbarrier.arrive.shared.b64 _, [%0];" :: "r"((uint32_t)(mb)) : "memory")
#define BULK_G2S(dst, src, n, mb) \
    asm volatile("cp.async.bulk.shared::cluster.global.mbarrier::complete_tx::bytes [%0], [%1], %2, [%3];" \
        :: "r"((uint32_t)(dst)), "l"(src), "r"((uint32_t)(n)), "r"((uint32_t)(mb)) : "memory")
#define MB_WAIT(mb, ph) do { \
    uint32_t _m=(uint32_t)(mb), _p=(uint32_t)(ph), _d; \
    asm volatile("{\n\t.reg .pred p;\n\tmbarrier.try_wait.parity.acquire.cta.shared::cta.b64 p, [%1], %2;\n\tselp.b32 %0, 1, 0, p;\n\t}" : "=r"(_d) : "r"(_m), "r"(_p) : "memory"); \
    if (!_d) { asm volatile("{\n\t.reg .pred P1;\n\tWL_%=:\n\tmbarrier.try_wait.parity.acquire.cta.shared::cta.b64 P1, [%0], %1, 0x989680;\n\t@P1 bra.uni WD_%=;\n\tbra.uni WL_%=;\n\tWD_%=:\n\t}" :: "r"(_m), "r"(_p) : "memory"); } \
} while (0)

// smem layout (bytes)
#define OFF_A     0         // 256 rows x 512B = 131072
#define OFF_B     131072    // 2 bufs x 16KB -> 163840
#define OFF_SHB   163840    // float[1024] -> 167936
#define OFF_SMIN  167936    // uint[256] -> 168960
#define OFF_CNT   168960    // int[256] -> 169984
#define OFF_LIMQ  169984    // uint[256] -> 171008
#define OFF_SBEST 171008    // ull[256] -> 173056
#define OFF_MBAR  173056    // full0,full1,empty0,empty1 + pad -> 173184
#define OFF_CAND  173184    // u32[256*CAP] = 24576 -> 197760
#define OFF_SHA   197760    // float[256] -> 198784
#define SMEM_SZ   198784

// ===== kernel 1: emb norms (bitwise identical math) + emb -> pre-swizzled bf16 =====
__global__ void prep_emb(const float* __restrict__ emb) {
    int er = (blockIdx.x * blockDim.x + threadIdx.x) >> 5;
    int lane = threadIdx.x & 31;
    if (blockIdx.x == 0 && threadIdx.x == 0) { g_loss = 0.0; g_done = 0; }
    if (er >= K_CODES) return;
    const float* src = emb + (size_t)er * D_DIM;
    const int chunk = er >> 5, r = er & 31;          // 32 codes per chunk
    const uint32_t ebase = (uint32_t)chunk * (uint32_t)CHUNK_BYTES + (uint32_t)r * 512u;
    float s = 0.f;
#pragma unroll
    for (int i = 0; i < D_DIM / 32; i++) {
        float v = src[lane + i * 32];
        s = __fmaf_rn(v, v, s);
        int j = lane + i * 32;
        uint32_t u = (uint32_t)(j >> 3);
        uint32_t off = ebase + (((u ^ (uint32_t)(r & 7)) << 4) | (uint32_t)((j & 7) * 2));
        *reinterpret_cast<__nv_bfloat16*>(g_eb + off) = __float2bfloat16_rn(v);
    }
#pragma unroll
    for (int o = 16; o > 0; o >>= 1) s = __fadd_rn(s, __shfl_down_sync(0xffffffffu, s, o));
    if (lane == 0) g_b[er] = s;
}

// exact fp32 rescore: identical op sequence to the rel_err=0 scalar kernel
__device__ __noinline__ void rescore(const float* __restrict__ z, const float* __restrict__ emb,
                                     int row, int k, float aval, float bval,
                                     unsigned long long* __restrict__ sbest) {
    const float* zr = z + (size_t)row * D_DIM;
    const float* er = emb + (size_t)k * D_DIM;
    float c = 0.f;
#pragma unroll 8
    for (int i = 0; i < D_DIM; i += 4) {
        float4 a = *reinterpret_cast<const float4*>(zr + i);
        float4 b = *reinterpret_cast<const float4*>(er + i);
        c = __fmaf_rn(a.x, b.x, c); c = __fmaf_rn(a.y, b.y, c);
        c = __fmaf_rn(a.z, b.z, c); c = __fmaf_rn(a.w, b.w, c);
    }
    float d = __fmaf_rn(-2.0f, c, __fadd_rn(aval, bval));
    unsigned long long pk = ((unsigned long long)fmap(d) << 32) | (unsigned)k;
    atomicMin(sbest, pk);
}

// ===== kernel 2: A-resident-in-registers GEMM + argmin + output + loss =====
__global__ __launch_bounds__(NTHR, 1)
void gemm_mma(const float* __restrict__ z, const float* __restrict__ emb,
              float* __restrict__ out, int out_size) {
    extern __shared__ __align__(128) char smem[];
    const uint32_t sbase = s2u(smem);
    const int tid = threadIdx.x;
    const int t = tid & 31;
    const int w = tid >> 5;           // 8 warps, all m-warps: 32 rows each
    const int row0 = blockIdx.x * ROWS_CTA;

    float*    shb  = reinterpret_cast<float*>(smem + OFF_SHB);
    float*    sha  = reinterpret_cast<float*>(smem + OFF_SHA);
    uint32_t* smin = reinterpret_cast<uint32_t*>(smem + OFF_SMIN);
    int*      cnt  = reinterpret_cast<int*>(smem + OFF_CNT);
    uint32_t* limq = reinterpret_cast<uint32_t*>(smem + OFF_LIMQ);
    unsigned long long* sbest = reinterpret_cast<unsigned long long*>(smem + OFF_SBEST);
    uint32_t* cand = reinterpret_cast<uint32_t*>(smem + OFF_CAND);
    const uint32_t full0  = sbase + OFF_MBAR,      full1  = sbase + OFF_MBAR + 8;
    const uint32_t empty0 = sbase + OFF_MBAR + 16, empty1 = sbase + OFF_MBAR + 24;

    if (tid < ROWS_CTA) { smin[tid] = 0xFF800000u; cnt[tid] = 0; sbest[tid] = ~0ull; }
    for (int i = tid; i < K_CODES; i += NTHR) shb[i] = g_b[i];
    if (tid == 0) {
        MB_INIT(full0, 1);     MB_INIT(full1, 1);
        MB_INIT(empty0, NWARP); MB_INIT(empty1, NWARP);
    }
    __syncthreads();

    if (tid == 0) {
        MB_EXPECT(full0, CHUNK_BYTES);
        BULK_G2S(sbase + OFF_B, (const void*)(g_eb), CHUNK_BYTES, full0);
        MB_EXPECT(full1, CHUNK_BYTES);
        BULK_G2S(sbase + OFF_B + CHUNK_BYTES, (const void*)(g_eb + CHUNK_BYTES), CHUNK_BYTES, full1);
    }

    // A: 256 rows x 256 bf16 (fp32 -> bf16), 512B pitch, unit-xor swizzle.
    for (int i = tid; i < ROWS_CTA * 32; i += NTHR) {
        int r = i >> 5, u = i & 31;
        const float4* s4 = reinterpret_cast<const float4*>(z + (size_t)(row0 + r) * D_DIM + u * 8);
        float4 f0 = s4[0], f1 = s4[1];
        uint4 v = { pbf2(f0.x, f0.y), pbf2(f0.z, f0.w), pbf2(f1.x, f1.y), pbf2(f1.z, f1.w) };
        *reinterpret_cast<uint4*>(smem + OFF_A + r * 512 + ((u ^ (r & 7)) << 4)) = v;
    }

    // z row-norms for this CTA's rows — bitwise-identical op sequence
    for (int rr = 0; rr < ROWS_CTA / NWARP; rr++) {
        int r = w * (ROWS_CTA / NWARP) + rr;
        const float* src = z + (size_t)(row0 + r) * D_DIM;
        float s = 0.f;
#pragma unroll
        for (int i = 0; i < D_DIM / 32; i++) {
            float v = src[t + i * 32];
            s = __fmaf_rn(v, v, s);
        }
#pragma unroll
        for (int o = 16; o > 0; o >>= 1) s = __fadd_rn(s, __shfl_down_sync(0xffffffffu, s, o));
        if (t == 0) sha[r] = s;
    }
    __syncthreads();   // A + sha visible; last CTA-wide barrier until the end

    // ldmatrix lane addressing with folded swizzle
    const int t7 = t & 7;
    const int arow = t7 + ((t >> 3) & 1) * 8;
    const int asel = (t >> 4) & 1;
    const int brow = t7 + ((t >> 4) & 1) * 8;
    const int bsel = (t >> 3) & 1;
    const uint32_t t7e4 = (uint32_t)((t7 & 6) << 4);
    const uint32_t abase2 = sbase + OFF_A + (uint32_t)(w * 32 + arow) * 512
                          + (uint32_t)((asel ^ (t7 & 1)) << 4);
    const uint32_t boff2  = (uint32_t)(brow * 512)
                          + (uint32_t)((bsel ^ (t7 & 1)) << 4);
    const int crow = t >> 2;
    const int ccol = 2 * (t & 3);

    // ---- prologue: ALL A fragments into registers (once per kernel) ----
    uint32_t afr[16][2][4];
#pragma unroll
    for (int ks = 0; ks < 16; ks++) {
        uint32_t koff = (uint32_t)(ks << 5) ^ t7e4;
        LDSM4(afr[ks][0], abase2 + koff);
        LDSM4(afr[ks][1], abase2 + 8192 + koff);
    }

    for (int c = 0; c < NCHUNK; c++) {
        const int b = c & 1;
        const int c0 = c * CHUNK_CODES;
        const uint32_t fullb  = b ? full1 : full0;
        const uint32_t emptyb = b ? empty1 : empty0;
        const uint32_t bbase2 = sbase + OFF_B + (uint32_t)(b * CHUNK_BYTES) + boff2;

        MB_WAIT(fullb, (c >> 1) & 1);

        float acc[2][4][4];
#pragma unroll
        for (int im = 0; im < 2; im++)
#pragma unroll
            for (int in = 0; in < 4; in++)
#pragma unroll
                for (int r = 0; r < 4; r++) acc[im][in][r] = 0.f;

        // B fragments double-buffered; A comes from registers
        uint32_t bf[2][2][4];
        {
            uint32_t koff = t7e4;
            LDSM4(bf[0][0], bbase2 + koff);
            LDSM4(bf[0][1], bbase2 + 8192 + koff);
        }
#pragma unroll
        for (int ks = 0; ks < 16; ks++) {
            const int cur = ks & 1, nxt = cur ^ 1;
            if (ks < 15) {
                uint32_t koff = (uint32_t)((ks + 1) << 5) ^ t7e4;
                LDSM4(bf[nxt][0], bbase2 + koff);
                LDSM4(bf[nxt][1], bbase2 + 8192 + koff);
            }
#pragma unroll
            for (int im = 0; im < 2; im++) {
                MMA16816(acc[im][0], afr[ks][im], bf[cur][0][0], bf[cur][0][1]);
                MMA16816(acc[im][1], afr[ks][im], bf[cur][0][2], bf[cur][0][3]);
                MMA16816(acc[im][2], afr[ks][im], bf[cur][1][0], bf[cur][1][1]);
                MMA16816(acc[im][3], afr[ks][im], bf[cur][1][2], bf[cur][1][3]);
            }
        }

        if (t == 0) MB_ARRIVE(emptyb);

        // ---- fused epilogue: running min + immediate collection (no barrier) ----
#pragma unroll
        for (int im = 0; im < 2; im++) {
#pragma unroll
            for (int h = 0; h < 2; h++) {
                const int row = w * 32 + im * 16 + crow + h * 8;
                float mnl = CUDART_INF_F;
#pragma unroll
                for (int in = 0; in < 4; in++) {
                    int nl = in * 8 + ccol;
                    mnl = fminf(mnl, __fmaf_rn(-2.0f, acc[im][in][2 * h],     shb[c0 + nl]));
                    mnl = fminf(mnl, __fmaf_rn(-2.0f, acc[im][in][2 * h + 1], shb[c0 + nl + 1]));
                }
                float mn = mnl;
                mn = fminf(mn, __shfl_xor_sync(0xffffffffu, mn, 1));
                mn = fminf(mn, __shfl_xor_sync(0xffffffffu, mn, 2));
                uint32_t oldv = 0xFF800000u;
                if ((t & 3) == 0) oldv = atomicMin(&smin[row], fmap(mn));
                oldv = __shfl_sync(0xffffffffu, oldv, t & ~3);
                const float lim = fminf(funmap(oldv), mn) + MARGIN;
                if (mnl > lim) continue;
#pragma unroll
                for (int in = 0; in < 4; in++) {
#pragma unroll
                    for (int p = 0; p < 2; p++) {
                        int nl = in * 8 + ccol + p;
                        float s = __fmaf_rn(-2.0f, acc[im][in][2 * h + p], shb[c0 + nl]);
                        if (s <= lim) {
                            int idx = atomicAdd(&cnt[row], 1);
                            if (idx < CAP)
                                cand[row * CAP + idx] =
                                    (fmap(s) & 0xFFFF0000u) | (unsigned)(c0 + nl);
                        }
                    }
                }
            }
        }

        // rotated refiller: after epilogue, a different warp each chunk
        if (c < NCHUNK - 2 && w == (c % NWARP) && t == 0) {
            MB_WAIT(emptyb, (c >> 1) & 1);
            MB_EXPECT(fullb, CHUNK_BYTES);
            BULK_G2S(sbase + OFF_B + b * CHUNK_BYTES,
                     (const void*)(g_eb + (size_t)(c + 2) * CHUNK_BYTES), CHUNK_BYTES, fullb);
        }
    }
    __syncthreads();   // all candidates + smin final

    if (tid < ROWS_CTA) limq[tid] = fmap(funmap(smin[tid]) + MARGIN) >> 16;
    __syncthreads();

    for (int i = tid; i < ROWS_CTA * CAP; i += NTHR) {
        int row = i / CAP, slot = i % CAP;
        int ne = min(cnt[row], CAP);
        if (slot < ne) {
            uint32_t pk = cand[row * CAP + slot];
            if ((pk >> 16) <= limq[row]) {
                int k = (int)(pk & 0x3FFu);
                rescore(z, emb, row0 + row, k, sha[row], shb[k], &sbest[row]);
            }
        }
    }
    for (int row = w; row < ROWS_CTA; row += NWARP) {
        if (cnt[row] > CAP)
            for (int k = t; k < K_CODES; k += 32)
                rescore(z, emb, row0 + row, k, sha[row], shb[k], &sbest[row]);
    }
    __syncthreads();   // sbest final

    // ---- fused output: gather + straight-through + MSE (this CTA's rows) ----
    double ls = 0.0;
    for (int i = tid; i < ROWS_CTA * 64; i += NTHR) {
        int r = i >> 6, u = (i & 63) * 4;
        int grow = row0 + r;
        int code = (int)(unsigned)(sbest[r] & 0x3FFull);
        float4 q  = *reinterpret_cast<const float4*>(&emb[(size_t)code * D_DIM + u]);
        float4 zv = *reinterpret_cast<const float4*>(&z[(size_t)grow * D_DIM + u]);
        float dx = __fadd_rn(q.x, -zv.x), dy = __fadd_rn(q.y, -zv.y);
        float dz = __fadd_rn(q.z, -zv.z), dw = __fadd_rn(q.w, -zv.w);
        float4 ov = { __fadd_rn(zv.x, dx), __fadd_rn(zv.y, dy),
                      __fadd_rn(zv.z, dz), __fadd_rn(zv.w, dw) };
        *reinterpret_cast<float4*>(&out[(size_t)grow * D_DIM + u]) = ov;
        ls += (double)dx * dx + (double)dy * dy + (double)dz * dz + (double)dw * dw;
    }
#pragma unroll
    for (int o = 16; o > 0; o >>= 1) ls += __shfl_down_sync(0xffffffffu, ls, o);
    double* wsum = reinterpret_cast<double*>(smem + OFF_CAND);   // cand area reusable now
    if (t == 0) wsum[w] = ls;
    __syncthreads();
    if (tid == 0) {
        double bs = 0.0;
#pragma unroll
        for (int ww = 0; ww < NWARP; ww++) bs += wsum[ww];
        atomicAdd(&g_loss, bs);
        __threadfence();
        unsigned v = atomicAdd(&g_done, 1u);
        if (v == gridDim.x - 1) {
            __threadfence();
            double tot = *((volatile double*)&g_loss);
            float mf = (float)(tot / (double)((size_t)N_ROWS * D_DIM));
            out[out_size - 1] = __fadd_rn(mf, __fmul_rn(0.25f, mf));
            g_done = 0;    // reset for next graph replay
        }
    }
}

extern "C" void kernel_launch(void* const* d_in, const int* in_sizes, int n_in,
                              void* d_out, int out_size) {
    const float* z   = (const float*)d_in[0];
    const float* emb = (const float*)d_in[1];
    float* out = (float*)d_out;

    cudaFuncSetAttribute(gemm_mma, cudaFuncAttributeMaxDynamicSharedMemorySize, SMEM_SZ);

    prep_emb<<<K_CODES / 8, 256>>>(emb);
    gemm_mma<<<N_ROWS / ROWS_CTA, NTHR, SMEM_SZ>>>(z, emb, out, out_size);
}

// round 17
// speedup vs baseline: 1.7296x; 1.7296x over previous
#include <cuda_runtime.h>
#include <cuda_bf16.h>
#include <math_constants.h>
#include <cstdint>

#define N_ROWS 32768
#define D_DIM  256
#define K_CODES 1024
#define MARGIN 3.0e-3f
#define CAP 24
#define NTHR 512
#define ROWS_CTA 256
#define NWARP 16
#define NCHUNK 16
#define CHUNK_CODES 64
#define CHUNK_BYTES 32768

__device__ float  g_b[K_CODES];
__device__ double g_loss = 0.0;
__device__ unsigned g_done = 0;
// pre-swizzled bf16 codebook: 16 chunks x 64 codes x 512B (unit-xor swizzled)
__device__ __align__(128) unsigned char g_eb[K_CODES * D_DIM * 2];

__device__ __forceinline__ uint32_t s2u(const void* p) {
    uint32_t a;
    asm("{ .reg .u64 t; cvta.to.shared.u64 t, %1; cvt.u32.u64 %0, t; }" : "=r"(a) : "l"(p));
    return a;
}
__device__ __forceinline__ uint32_t pbf2(float lo, float hi) {
    uint32_t r;
    asm("{.reg .b16 l,h;\n\tcvt.rn.bf16.f32 l,%1;\n\tcvt.rn.bf16.f32 h,%2;\n\tmov.b32 %0,{l,h};}"
        : "=r"(r) : "f"(lo), "f"(hi));
    return r;
}
__device__ __forceinline__ uint32_t fmap(float f) {
    uint32_t b = __float_as_uint(f);
    return b ^ ((b & 0x80000000u) ? 0xFFFFFFFFu : 0x80000000u);
}
__device__ __forceinline__ float funmap(uint32_t u) {
    uint32_t b = (u & 0x80000000u) ? (u ^ 0x80000000u) : ~u;
    return __uint_as_float(b);
}
#define LDSM4(d, addr) \
    asm volatile("ldmatrix.sync.aligned.m8n8.x4.shared.b16 {%0,%1,%2,%3}, [%4];" \
        : "=r"((d)[0]), "=r"((d)[1]), "=r"((d)[2]), "=r"((d)[3]) : "r"(addr))
#define MMA16816(c, a, b0, b1) \
    asm volatile("mma.sync.aligned.m16n8k16.row.col.f32.bf16.bf16.f32 " \
        "{%0,%1,%2,%3}, {%4,%5,%6,%7}, {%8,%9}, {%0,%1,%2,%3};" \
        : "+f"((c)[0]), "+f"((c)[1]), "+f"((c)[2]), "+f"((c)[3]) \
        : "r"((a)[0]), "r"((a)[1]), "r"((a)[2]), "r"((a)[3]), "r"(b0), "r"(b1))
#define MB_INIT(mb, c) \
    asm volatile("mbarrier.init.shared.b64 [%0], %1;" :: "r"((uint32_t)(mb)), "r"((uint32_t)(c)) : "memory")
#define MB_EXPECT(mb, n) \
    asm volatile("mbarrier.arrive.expect_tx.shared.b64 _, [%0], %1;" :: "r"((uint32_t)(mb)), "r"((uint32_t)(n)) : "memory")
#define MB_ARRIVE(mb) \
    asm volatile("mbarrier.arrive.shared.b64 _, [%0];" :: "r"((uint32_t)(mb)) : "memory")
#define BULK_G2S(dst, src, n, mb) \
    asm volatile("cp.async.bulk.shared::cluster.global.mbarrier::complete_tx::bytes [%0], [%1], %2, [%3];" \
        :: "r"((uint32_t)(dst)), "l"(src), "r"((uint32_t)(n)), "r"((uint32_t)(mb)) : "memory")
#define MB_WAIT(mb, ph) do { \
    uint32_t _m=(uint32_t)(mb), _p=(uint32_t)(ph), _d; \
    asm volatile("{\n\t.reg .pred p;\n\tmbarrier.try_wait.parity.acquire.cta.shared::cta.b64 p, [%1], %2;\n\tselp.b32 %0, 1, 0, p;\n\t}" : "=r"(_d) : "r"(_m), "r"(_p) : "memory"); \
    if (!_d) { asm volatile("{\n\t.reg .pred P1;\n\tWL_%=:\n\tmbarrier.try_wait.parity.acquire.cta.shared::cta.b64 P1, [%0], %1, 0x989680;\n\t@P1 bra.uni WD_%=;\n\tbra.uni WL_%=;\n\tWD_%=:\n\t}" :: "r"(_m), "r"(_p) : "memory"); } \
} while (0)

// smem layout (bytes)
#define OFF_A     0         // 256 rows x 512B = 131072
#define OFF_B     131072    // 2 bufs x 32KB -> 196608
#define OFF_SHB   196608    // float[1024] -> 200704
#define OFF_SMIN  200704    // uint[256] -> 201728
#define OFF_CNT   201728    // int[256] -> 202752
#define OFF_LIMQ  202752    // uint[256] -> 203776
#define OFF_SBEST 203776    // ull[256] -> 205824
#define OFF_MBAR  205824    // full0,full1,empty0,empty1 + pad -> 205952
#define OFF_CAND  205952    // u32[256*CAP] = 24576 -> 230528
#define OFF_SHA   230528    // float[256] -> 231552
#define SMEM_SZ   231552

// ===== kernel 1: emb norms (bitwise identical math) + emb -> pre-swizzled bf16 =====
__global__ void prep_emb(const float* __restrict__ emb) {
    int er = (blockIdx.x * blockDim.x + threadIdx.x) >> 5;
    int lane = threadIdx.x & 31;
    if (blockIdx.x == 0 && threadIdx.x == 0) { g_loss = 0.0; g_done = 0; }
    if (er >= K_CODES) return;
    const float* src = emb + (size_t)er * D_DIM;
    const int chunk = er >> 6, r = er & 63;
    const uint32_t ebase = (uint32_t)chunk * (uint32_t)CHUNK_BYTES + (uint32_t)r * 512u;
    float s = 0.f;
#pragma unroll
    for (int i = 0; i < D_DIM / 32; i++) {
        float v = src[lane + i * 32];
        s = __fmaf_rn(v, v, s);
        int j = lane + i * 32;
        uint32_t u = (uint32_t)(j >> 3);
        uint32_t off = ebase + (((u ^ (uint32_t)(r & 7)) << 4) | (uint32_t)((j & 7) * 2));
        *reinterpret_cast<__nv_bfloat16*>(g_eb + off) = __float2bfloat16_rn(v);
    }
#pragma unroll
    for (int o = 16; o > 0; o >>= 1) s = __fadd_rn(s, __shfl_down_sync(0xffffffffu, s, o));
    if (lane == 0) g_b[er] = s;
}

// exact fp32 rescore: identical op sequence to the rel_err=0 scalar kernel
__device__ __noinline__ void rescore(const float* __restrict__ z, const float* __restrict__ emb,
                                     int row, int k, float aval, float bval,
                                     unsigned long long* __restrict__ sbest) {
    const float* zr = z + (size_t)row * D_DIM;
    const float* er = emb + (size_t)k * D_DIM;
    float c = 0.f;
#pragma unroll 8
    for (int i = 0; i < D_DIM; i += 4) {
        float4 a = *reinterpret_cast<const float4*>(zr + i);
        float4 b = *reinterpret_cast<const float4*>(er + i);
        c = __fmaf_rn(a.x, b.x, c); c = __fmaf_rn(a.y, b.y, c);
        c = __fmaf_rn(a.z, b.z, c); c = __fmaf_rn(a.w, b.w, c);
    }
    float d = __fmaf_rn(-2.0f, c, __fadd_rn(aval, bval));
    unsigned long long pk = ((unsigned long long)fmap(d) << 32) | (unsigned)k;
    atomicMin(sbest, pk);
}

// ===== kernel 2: 16-warp fused GEMM + argmin + output + loss =====
__global__ __launch_bounds__(NTHR, 1)
void gemm_mma(const float* __restrict__ z, const float* __restrict__ emb,
              float* __restrict__ out, int out_size) {
    extern __shared__ __align__(128) char smem[];
    const uint32_t sbase = s2u(smem);
    const int tid = threadIdx.x;
    const int t = tid & 31;
    const int w = tid >> 5;
    const int warpm = w & 7;          // 8 m-warps: 32 rows each
    const int warpn = w >> 3;         // 2 n-warps: 32 codes each
    const int row0 = blockIdx.x * ROWS_CTA;

    float*    shb  = reinterpret_cast<float*>(smem + OFF_SHB);
    float*    sha  = reinterpret_cast<float*>(smem + OFF_SHA);
    uint32_t* smin = reinterpret_cast<uint32_t*>(smem + OFF_SMIN);
    int*      cnt  = reinterpret_cast<int*>(smem + OFF_CNT);
    uint32_t* limq = reinterpret_cast<uint32_t*>(smem + OFF_LIMQ);
    unsigned long long* sbest = reinterpret_cast<unsigned long long*>(smem + OFF_SBEST);
    uint32_t* cand = reinterpret_cast<uint32_t*>(smem + OFF_CAND);
    const uint32_t full0  = sbase + OFF_MBAR,      full1  = sbase + OFF_MBAR + 8;
    const uint32_t empty0 = sbase + OFF_MBAR + 16, empty1 = sbase + OFF_MBAR + 24;

    if (tid < ROWS_CTA) { smin[tid] = 0xFF800000u; cnt[tid] = 0; sbest[tid] = ~0ull; }
    for (int i = tid; i < K_CODES; i += NTHR) shb[i] = g_b[i];
    if (tid == 0) {
        MB_INIT(full0, 1);     MB_INIT(full1, 1);
        MB_INIT(empty0, NWARP); MB_INIT(empty1, NWARP);
    }
    __syncthreads();

    if (tid == 0) {
        MB_EXPECT(full0, CHUNK_BYTES);
        BULK_G2S(sbase + OFF_B, (const void*)(g_eb), CHUNK_BYTES, full0);
        MB_EXPECT(full1, CHUNK_BYTES);
        BULK_G2S(sbase + OFF_B + CHUNK_BYTES, (const void*)(g_eb + CHUNK_BYTES), CHUNK_BYTES, full1);
    }

    // A: 256 rows x 256 bf16 (fp32 -> bf16), 512B pitch, unit-xor swizzle.
    for (int i = tid; i < ROWS_CTA * 32; i += NTHR) {
        int r = i >> 5, u = i & 31;
        const float4* s4 = reinterpret_cast<const float4*>(z + (size_t)(row0 + r) * D_DIM + u * 8);
        float4 f0 = s4[0], f1 = s4[1];
        uint4 v = { pbf2(f0.x, f0.y), pbf2(f0.z, f0.w), pbf2(f1.x, f1.y), pbf2(f1.z, f1.w) };
        *reinterpret_cast<uint4*>(smem + OFF_A + r * 512 + ((u ^ (r & 7)) << 4)) = v;
    }

    // z row-norms for this CTA's rows — bitwise-identical op sequence
    for (int rr = 0; rr < ROWS_CTA / NWARP; rr++) {
        int r = w * (ROWS_CTA / NWARP) + rr;
        const float* src = z + (size_t)(row0 + r) * D_DIM;
        float s = 0.f;
#pragma unroll
        for (int i = 0; i < D_DIM / 32; i++) {
            float v = src[t + i * 32];
            s = __fmaf_rn(v, v, s);
        }
#pragma unroll
        for (int o = 16; o > 0; o >>= 1) s = __fadd_rn(s, __shfl_down_sync(0xffffffffu, s, o));
        if (t == 0) sha[r] = s;
    }
    __syncthreads();   // A + sha visible; last CTA-wide barrier until the end

    // ldmatrix lane addressing with folded swizzle
    const int t7 = t & 7;
    const int arow = t7 + ((t >> 3) & 1) * 8;
    const int asel = (t >> 4) & 1;
    const int brow = t7 + ((t >> 4) & 1) * 8;
    const int bsel = (t >> 3) & 1;
    const uint32_t t7e4 = (uint32_t)((t7 & 6) << 4);
    const uint32_t abase2 = sbase + OFF_A + (uint32_t)(warpm * 32 + arow) * 512
                          + (uint32_t)((asel ^ (t7 & 1)) << 4);
    const uint32_t boff2  = (uint32_t)((warpn * 32 + brow) * 512)
                          + (uint32_t)((bsel ^ (t7 & 1)) << 4);
    const int n0 = warpn * 32;
    const int crow = t >> 2;
    const int ccol = 2 * (t & 3);

    for (int c = 0; c < NCHUNK; c++) {
        const int b = c & 1;
        const int c0 = c * CHUNK_CODES;
        const uint32_t fullb  = b ? full1 : full0;
        const uint32_t emptyb = b ? empty1 : empty0;
        const uint32_t bbase2 = sbase + OFF_B + (uint32_t)(b * CHUNK_BYTES) + boff2;

        MB_WAIT(fullb, (c >> 1) & 1);

        float acc[2][4][4];
#pragma unroll
        for (int im = 0; im < 2; im++)
#pragma unroll
            for (int in = 0; in < 4; in++)
#pragma unroll
                for (int r = 0; r < 4; r++) acc[im][in][r] = 0.f;

        // single-buffered fragments (16 warps hide LDSM latency)
#pragma unroll
        for (int ks = 0; ks < 16; ks++) {
            uint32_t koff = (uint32_t)(ks << 5) ^ t7e4;
            uint32_t af[2][4], bf[2][4];
            LDSM4(af[0], abase2 + koff);
            LDSM4(af[1], abase2 + 8192 + koff);
            LDSM4(bf[0], bbase2 + koff);
            LDSM4(bf[1], bbase2 + 8192 + koff);
#pragma unroll
            for (int im = 0; im < 2; im++) {
                MMA16816(acc[im][0], af[im], bf[0][0], bf[0][1]);
                MMA16816(acc[im][1], af[im], bf[0][2], bf[0][3]);
                MMA16816(acc[im][2], af[im], bf[1][0], bf[1][1]);
                MMA16816(acc[im][3], af[im], bf[1][2], bf[1][3]);
            }
        }

        if (t == 0) MB_ARRIVE(emptyb);

        // ---- fused epilogue: running min + immediate collection (no barrier) ----
#pragma unroll
        for (int im = 0; im < 2; im++) {
#pragma unroll
            for (int h = 0; h < 2; h++) {
                const int row = warpm * 32 + im * 16 + crow + h * 8;
                float mnl = CUDART_INF_F;
#pragma unroll
                for (int in = 0; in < 4; in++) {
                    int nl = n0 + in * 8 + ccol;
                    mnl = fminf(mnl, __fmaf_rn(-2.0f, acc[im][in][2 * h],     shb[c0 + nl]));
                    mnl = fminf(mnl, __fmaf_rn(-2.0f, acc[im][in][2 * h + 1], shb[c0 + nl + 1]));
                }
                float mn = mnl;
                mn = fminf(mn, __shfl_xor_sync(0xffffffffu, mn, 1));
                mn = fminf(mn, __shfl_xor_sync(0xffffffffu, mn, 2));
                uint32_t oldv = 0xFF800000u;
                if ((t & 3) == 0) oldv = atomicMin(&smin[row], fmap(mn));
                oldv = __shfl_sync(0xffffffffu, oldv, t & ~3);
                const float lim = fminf(funmap(oldv), mn) + MARGIN;
                if (mnl > lim) continue;
#pragma unroll
                for (int in = 0; in < 4; in++) {
#pragma unroll
                    for (int p = 0; p < 2; p++) {
                        int nl = n0 + in * 8 + ccol + p;
                        float s = __fmaf_rn(-2.0f, acc[im][in][2 * h + p], shb[c0 + nl]);
                        if (s <= lim) {
                            int idx = atomicAdd(&cnt[row], 1);
                            if (idx < CAP)
                                cand[row * CAP + idx] =
                                    (fmap(s) & 0xFFFF0000u) | (unsigned)(c0 + nl);
                        }
                    }
                }
            }
        }

        // rotated refiller: after epilogue, a different warp each chunk
        if (c < NCHUNK - 2 && w == (c % NWARP) && t == 0) {
            MB_WAIT(emptyb, (c >> 1) & 1);
            MB_EXPECT(fullb, CHUNK_BYTES);
            BULK_G2S(sbase + OFF_B + b * CHUNK_BYTES,
                     (const void*)(g_eb + (size_t)(c + 2) * CHUNK_BYTES), CHUNK_BYTES, fullb);
        }
    }
    __syncthreads();   // all candidates + smin final

    if (tid < ROWS_CTA) limq[tid] = fmap(funmap(smin[tid]) + MARGIN) >> 16;
    __syncthreads();

    for (int i = tid; i < ROWS_CTA * CAP; i += NTHR) {
        int row = i / CAP, slot = i % CAP;
        int ne = min(cnt[row], CAP);
        if (slot < ne) {
            uint32_t pk = cand[row * CAP + slot];
            if ((pk >> 16) <= limq[row]) {
                int k = (int)(pk & 0x3FFu);
                rescore(z, emb, row0 + row, k, sha[row], shb[k], &sbest[row]);
            }
        }
    }
    for (int row = w; row < ROWS_CTA; row += NWARP) {
        if (cnt[row] > CAP)
            for (int k = t; k < K_CODES; k += 32)
                rescore(z, emb, row0 + row, k, sha[row], shb[k], &sbest[row]);
    }
    __syncthreads();   // sbest final

    // ---- fused output: gather + straight-through + MSE (this CTA's rows) ----
    double ls = 0.0;
    for (int i = tid; i < ROWS_CTA * 64; i += NTHR) {
        int r = i >> 6, u = (i & 63) * 4;
        int grow = row0 + r;
        int code = (int)(unsigned)(sbest[r] & 0x3FFull);
        float4 q  = *reinterpret_cast<const float4*>(&emb[(size_t)code * D_DIM + u]);
        float4 zv = *reinterpret_cast<const float4*>(&z[(size_t)grow * D_DIM + u]);
        float dx = __fadd_rn(q.x, -zv.x), dy = __fadd_rn(q.y, -zv.y);
        float dz = __fadd_rn(q.z, -zv.z), dw = __fadd_rn(q.w, -zv.w);
        float4 ov = { __fadd_rn(zv.x, dx), __fadd_rn(zv.y, dy),
                      __fadd_rn(zv.z, dz), __fadd_rn(zv.w, dw) };
        *reinterpret_cast<float4*>(&out[(size_t)grow * D_DIM + u]) = ov;
        ls += (double)dx * dx + (double)dy * dy + (double)dz * dz + (double)dw * dw;
    }
#pragma unroll
    for (int o = 16; o > 0; o >>= 1) ls += __shfl_down_sync(0xffffffffu, ls, o);
    double* wsum = reinterpret_cast<double*>(smem + OFF_CAND);   // cand area reusable now
    if (t == 0) wsum[w] = ls;
    __syncthreads();
    if (tid == 0) {
        double bs = 0.0;
#pragma unroll
        for (int ww = 0; ww < NWARP; ww++) bs += wsum[ww];
        atomicAdd(&g_loss, bs);
        __threadfence();
        unsigned v = atomicAdd(&g_done, 1u);
        if (v == gridDim.x - 1) {
            __threadfence();
            double tot = *((volatile double*)&g_loss);
            float mf = (float)(tot / (double)((size_t)N_ROWS * D_DIM));
            out[out_size - 1] = __fadd_rn(mf, __fmul_rn(0.25f, mf));
            g_done = 0;    // reset for next graph replay
        }
    }
}

extern "C" void kernel_launch(void* const* d_in, const int* in_sizes, int n_in,
                              void* d_out, int out_size) {
    const float* z   = (const float*)d_in[0];
    const float* emb = (const float*)d_in[1];
    float* out = (float*)d_out;

    cudaFuncSetAttribute(gemm_mma, cudaFuncAttributeMaxDynamicSharedMemorySize, SMEM_SZ);

    prep_emb<<<K_CODES / 8, 256>>>(emb);
    gemm_mma<<<N_ROWS / ROWS_CTA, NTHR, SMEM_SZ>>>(z, emb, out, out_size);
}